// round 8
// baseline (speedup 1.0000x reference)
#include <cuda_runtime.h>
#include <math.h>

// Problem constants
#define B_    16
#define C_    1024
#define HW_   1024            // 32*32
#define N_    (B_*HW_)        // 16384 pixels
#define NE_   256             // codebook size
#define NOUT_ (B_*C_*HW_)     // 16777216 conv output elements

// Output layout (return-tuple order, flattened, float32):
//   [0 .. NOUT_)            conv output [B, C, H, W]
//   [NOUT_]                 loss
//   [NOUT_+1]               perplexity
//   [NOUT_+2 .. +2+N_)      min_idx (as float)

// -------- device scratch (no allocations allowed) --------
__device__ float g_embT[C_*NE_];     // emb transposed: [c][e]
__device__ float g_emb_sq[NE_];      // ||emb_e||^2
__device__ float g_WT[C_*C_];        // conv_w transposed: [c][o]
__device__ float g_table[NE_*C_];    // emb @ W^T + b : [e][o]
__device__ int   g_idx[N_];          // argmin per pixel
__device__ int   g_count[NE_];       // histogram
__device__ float g_partial[512];     // per-block loss partials (zsq + score_min)

// -------- zero histogram + partials (graph replays; must reset every launch) --------
__global__ void k_init()
{
    int t = threadIdx.x;
    if (t < NE_) g_count[t] = 0;
    g_partial[t] = 0.f;
    g_partial[t + 256] = 0.f;
}

// -------- emb: squared norms (double accum) + transpose to [c][e] --------
__global__ void __launch_bounds__(256) k_prep_emb(const float* __restrict__ emb)
{
    __shared__ double red[256];
    int e = blockIdx.x;
    int tid = threadIdx.x;
    float4 v = reinterpret_cast<const float4*>(emb + (size_t)e * C_)[tid]; // 256 f4/row
    double s = (double)v.x*v.x + (double)v.y*v.y + (double)v.z*v.z + (double)v.w*v.w;
    int c = tid * 4;
    g_embT[(c+0)*NE_ + e] = v.x;
    g_embT[(c+1)*NE_ + e] = v.y;
    g_embT[(c+2)*NE_ + e] = v.z;
    g_embT[(c+3)*NE_ + e] = v.w;
    red[tid] = s;
    __syncthreads();
    for (int st = 128; st > 0; st >>= 1) {
        if (tid < st) red[tid] += red[tid + st];
        __syncthreads();
    }
    if (tid == 0) g_emb_sq[e] = (float)red[0];
}

// -------- transpose conv_w [o][c] -> g_WT [c][o] --------
__global__ void k_transpose_w(const float* __restrict__ W)
{
    __shared__ float sm[32][33];
    int c0 = blockIdx.x * 32, o0 = blockIdx.y * 32;
    int tx = threadIdx.x, ty = threadIdx.y;        // (32, 8)
#pragma unroll
    for (int i = 0; i < 4; i++)
        sm[ty + i*8][tx] = W[(size_t)(o0 + ty + i*8) * C_ + c0 + tx];
    __syncthreads();
#pragma unroll
    for (int i = 0; i < 4; i++)
        g_WT[(size_t)(c0 + ty + i*8) * C_ + o0 + tx] = sm[tx][ty + i*8];
}

// -------- table[e][o] = emb[e]·W[o] + b[o]  (256x1024, K=1024) --------
__global__ void __launch_bounds__(128) k_table(const float* __restrict__ bias)
{
    __shared__ float As[32][32];   // [k][e_local]
    __shared__ float Bs[32][64];   // [k][o_local]
    int o0 = blockIdx.x * 64;
    int e0 = blockIdx.y * 32;
    int tid = threadIdx.x;
    int tx = tid & 15;             // o group of 4
    int ty = tid >> 4;             // e group of 4 (8 groups * 4 = 32)
    float acc[4][4] = {};

    for (int kc = 0; kc < C_/32; kc++) {
#pragma unroll
        for (int s = 0; s < 2; s++) {                 // 256 float4 for A
            int idx = tid + s*128;
            int k = idx >> 3, f4 = idx & 7;
            reinterpret_cast<float4*>(&As[k][f4*4])[0] =
                reinterpret_cast<const float4*>(g_embT + (size_t)(kc*32 + k)*NE_ + e0)[f4];
        }
#pragma unroll
        for (int s = 0; s < 4; s++) {                 // 512 float4 for B
            int idx = tid + s*128;
            int k = idx >> 4, f4 = idx & 15;
            reinterpret_cast<float4*>(&Bs[k][f4*4])[0] =
                reinterpret_cast<const float4*>(g_WT + (size_t)(kc*32 + k)*C_ + o0)[f4];
        }
        __syncthreads();
#pragma unroll
        for (int k = 0; k < 32; k++) {
            float4 a = reinterpret_cast<float4*>(&As[k][ty*4])[0];
            float4 b = reinterpret_cast<float4*>(&Bs[k][tx*4])[0];
            float aa[4] = {a.x, a.y, a.z, a.w};
            float bb[4] = {b.x, b.y, b.z, b.w};
#pragma unroll
            for (int i = 0; i < 4; i++)
#pragma unroll
                for (int j = 0; j < 4; j++)
                    acc[i][j] = fmaf(aa[i], bb[j], acc[i][j]);
        }
        __syncthreads();
    }
#pragma unroll
    for (int i = 0; i < 4; i++)
#pragma unroll
        for (int j = 0; j < 4; j++)
            g_table[(size_t)(e0 + ty*4 + i)*C_ + o0 + tx*4 + j] =
                acc[i][j] + bias[o0 + tx*4 + j];
}

// -------- distances + argmin + loss partials (the big one) --------
// Block: 32 hw-pixels x ALL 256 codes, K=1024, fp32. Grid (32 hw-tiles, 16 b).
__global__ void __launch_bounds__(256) k_dist(const float* __restrict__ z,
                                              float* __restrict__ out,
                                              int write_extras)
{
    __shared__ float As[32*32];    // [k][hw]
    __shared__ float Bs[32*256];   // [k][e]
    __shared__ float esq[256];
    __shared__ float red[256];

    int tid = threadIdx.x;
    int hw0 = blockIdx.x * 32;
    int b   = blockIdx.y;
    esq[tid] = g_emb_sq[tid];

    const float* zb = z + (size_t)b * C_ * HW_;
    int lk = tid >> 3, lf = tid & 7;   // A-tile load coords
    int ty = tid >> 5, tx = tid & 31;  // compute coords: rows ty*4.., e cols via tx

    float acc[4][8] = {};
    float zsq = 0.f;

    for (int kc = 0; kc < C_/32; kc++) {
        // A tile: 32 k-rows x 32 hw (each z element loaded exactly once globally)
        float4 av = reinterpret_cast<const float4*>(zb + (size_t)(kc*32 + lk)*HW_ + hw0)[lf];
        zsq = fmaf(av.x, av.x, zsq); zsq = fmaf(av.y, av.y, zsq);
        zsq = fmaf(av.z, av.z, zsq); zsq = fmaf(av.w, av.w, zsq);
        reinterpret_cast<float4*>(As + lk*32 + lf*4)[0] = av;
        // B tile: contiguous 32KB slab of embT
        {
            const float4* bsrc = reinterpret_cast<const float4*>(g_embT + (size_t)kc*32*NE_);
            float4* bdst = reinterpret_cast<float4*>(Bs);
#pragma unroll
            for (int s = 0; s < 8; s++) bdst[tid + s*256] = bsrc[tid + s*256];
        }
        __syncthreads();
#pragma unroll
        for (int k = 0; k < 32; k++) {
            float4 a  = reinterpret_cast<float4*>(As + k*32  + ty*4)[0];
            float4 b0 = reinterpret_cast<float4*>(Bs + k*256 + tx*4)[0];        // e = 4tx..4tx+3
            float4 b1 = reinterpret_cast<float4*>(Bs + k*256 + 128 + tx*4)[0];  // e = 128+4tx..
            float aa[4] = {a.x, a.y, a.z, a.w};
            float bb[8] = {b0.x, b0.y, b0.z, b0.w, b1.x, b1.y, b1.z, b1.w};
#pragma unroll
            for (int i = 0; i < 4; i++)
#pragma unroll
                for (int j = 0; j < 8; j++)
                    acc[i][j] = fmaf(aa[i], bb[j], acc[i][j]);
        }
        __syncthreads();
    }

    // score_e = ||e||^2 - 2 z·e ; argmin over e (lowest index wins ties, matching argmin)
    float lsum = 0.f;
    const unsigned full = 0xffffffffu;
#pragma unroll
    for (int i = 0; i < 4; i++) {
        float bv = 3.4e38f; int bi = 0;
#pragma unroll
        for (int j = 0; j < 8; j++) {
            int col = (j < 4) ? (tx*4 + j) : (128 + tx*4 + (j - 4));
            float sc = fmaf(-2.f, acc[i][j], esq[col]);
            if (sc < bv || (sc == bv && col < bi)) { bv = sc; bi = col; }
        }
        for (int off = 16; off > 0; off >>= 1) {
            float ov = __shfl_down_sync(full, bv, off);
            int   oi = __shfl_down_sync(full, bi, off);
            if (ov < bv || (ov == bv && oi < bi)) { bv = ov; bi = oi; }
        }
        if (tx == 0) {
            int n = b*HW_ + hw0 + ty*4 + i;
            g_idx[n] = bi;
            if (write_extras) out[NOUT_ + 2 + n] = (float)bi;
            atomicAdd(&g_count[bi], 1);
            lsum += bv;
        }
    }

    // block partial of (sum z^2 over tile + sum of min scores) -> deterministic tree
    red[tid] = zsq + lsum;
    __syncthreads();
    for (int st = 128; st > 0; st >>= 1) {
        if (tid < st) red[tid] += red[tid + st];
        __syncthreads();
    }
    if (tid == 0) g_partial[blockIdx.y * gridDim.x + blockIdx.x] = red[0];
}

// -------- loss + perplexity (fixed-order reductions => deterministic) --------
__global__ void __launch_bounds__(256) k_finalize(float* __restrict__ out, int write_extras)
{
    __shared__ float red[256];
    int tid = threadIdx.x;
    float s = g_partial[tid] + g_partial[tid + 256];
    red[tid] = s;
    __syncthreads();
    for (int st = 128; st > 0; st >>= 1) {
        if (tid < st) red[tid] += red[tid + st];
        __syncthreads();
    }
    float total = red[0];   // sum_n ||z_n - e_idx(n)||^2
    __syncthreads();

    float em = (float)g_count[tid] / (float)N_;
    red[tid] = em * logf(em + 1e-10f);
    __syncthreads();
    for (int st = 128; st > 0; st >>= 1) {
        if (tid < st) red[tid] += red[tid + st];
        __syncthreads();
    }
    if (tid == 0 && write_extras) {
        out[NOUT_]     = 1.25f * total / (float)NOUT_;  // (1 + BETA) * mse
        out[NOUT_ + 1] = expf(-red[0]);
    }
}

// -------- output: out[b][o][hw] = table[idx[b,hw]][o], smem-transposed tiles --------
__global__ void __launch_bounds__(256) k_out(float* __restrict__ out)
{
    __shared__ float tile[32][129];   // [hw][o], pad 129 -> conflict-free both phases
    __shared__ int idxs[32];
    int o0  = blockIdx.x * 128;
    int hw0 = blockIdx.y * 32;
    int b   = blockIdx.z;
    int tid = threadIdx.x;

    if (tid < 32) idxs[tid] = g_idx[b*HW_ + hw0 + tid];
    __syncthreads();

    for (int i = tid; i < 1024; i += 256) {          // 32 rows x 32 float4
        int r = i >> 5, f4 = i & 31;
        float4 v = reinterpret_cast<const float4*>(g_table + (size_t)idxs[r]*C_ + o0)[f4];
        float* dst = &tile[r][f4*4];
        dst[0] = v.x; dst[1] = v.y; dst[2] = v.z; dst[3] = v.w;
    }
    __syncthreads();

    size_t base = (size_t)b * C_ * HW_ + (size_t)o0 * HW_ + hw0;
    for (int i = tid; i < 4096; i += 256) {          // coalesced 128B stores per warp
        int o = i >> 5, hw = i & 31;
        out[base + (size_t)o * HW_ + hw] = tile[hw][o];
    }
}

// -------- launcher (graph-capturable: kernels only) --------
extern "C" void kernel_launch(void* const* d_in, const int* in_sizes, int n_in,
                              void* d_out, int out_size)
{
    (void)in_sizes; (void)n_in;
    const float* z    = (const float*)d_in[0];   // [16,1024,32,32]
    const float* emb  = (const float*)d_in[1];   // [256,1024]
    const float* W    = (const float*)d_in[2];   // [1024,1024]
    const float* bias = (const float*)d_in[3];   // [1024]
    float* out = (float*)d_out;
    int extras = (out_size >= NOUT_ + 2 + N_) ? 1 : 0;

    k_init<<<1, 256>>>();
    k_prep_emb<<<NE_, 256>>>(emb);
    k_transpose_w<<<dim3(32, 32), dim3(32, 8)>>>(W);
    k_table<<<dim3(16, 8), 128>>>(bias);
    k_dist<<<dim3(32, 16), 256>>>(z, out, extras);
    k_finalize<<<1, 256>>>(out, extras);
    k_out<<<dim3(8, 32, 16), 256>>>(out);
}

// round 15
// speedup vs baseline: 1.6780x; 1.6780x over previous
#include <cuda_runtime.h>
#include <cuda_fp16.h>
#include <cstdint>
#include <math.h>

// Problem constants
#define B_    16
#define C_    1024
#define HW_   1024
#define N_    (B_*HW_)        // 16384 pixels
#define NE_   256
#define NOUT_ (B_*C_*HW_)     // 16777216

#define MARGIN 1.0f           // > worst-case fp16 single-pass score error (~0.83)

// ---------------- helpers (base sm_103 target only: no 'a' features) ----------------
__device__ __forceinline__ uint32_t smem_to_u32(const void* p) {
    uint32_t a;
    asm("{ .reg .u64 t; cvta.to.shared.u64 t, %1; cvt.u32.u64 %0, t; }" : "=r"(a) : "l"(p));
    return a;
}
__device__ __forceinline__ void cpa16(uint32_t dst, const void* src) {
    asm volatile("cp.async.ca.shared.global [%0], [%1], 16;" :: "r"(dst), "l"(src));
}
#define CP_COMMIT() asm volatile("cp.async.commit_group;" ::: "memory")
#define CP_WAIT0()  asm volatile("cp.async.wait_group 0;" ::: "memory")
#define CP_WAIT1()  asm volatile("cp.async.wait_group 1;" ::: "memory")

__device__ __forceinline__ void ldsm4(uint32_t* r, uint32_t addr) {
    asm volatile("ldmatrix.sync.aligned.m8n8.x4.shared.b16 {%0,%1,%2,%3}, [%4];"
                 : "=r"(r[0]), "=r"(r[1]), "=r"(r[2]), "=r"(r[3]) : "r"(addr));
}
__device__ __forceinline__ void mma16816(float* c, const uint32_t* a, const uint32_t* b) {
    asm volatile("mma.sync.aligned.m16n8k16.row.col.f32.f16.f16.f32 "
                 "{%0,%1,%2,%3}, {%4,%5,%6,%7}, {%8,%9}, {%0,%1,%2,%3};"
                 : "+f"(c[0]), "+f"(c[1]), "+f"(c[2]), "+f"(c[3])
                 : "r"(a[0]), "r"(a[1]), "r"(a[2]), "r"(a[3]), "r"(b[0]), "r"(b[1]));
}

// ---------------- device scratch ----------------
__device__ __half g_zh[(size_t)N_*C_];   // fp16(z), [m][c]
__device__ __half g_eh[NE_*C_];          // fp16(emb), [e][c]
__device__ float g_embT[C_*NE_];         // [c][e] (table GEMM)
__device__ float g_emb_sq[NE_];
__device__ float g_WT[C_*C_];
__device__ float g_tpart[4*NE_*C_];
__device__ float g_table[NE_*C_];
__device__ float g_scores[(size_t)N_*NE_];  // 16MB scores = esq - 2 z.e
__device__ float g_zsqp[16384];
__device__ float g_minscore[N_];
__device__ int   g_idx[N_];
__device__ int   g_count[NE_];

// ---------------- kernels ----------------
__global__ void k_init() { if (threadIdx.x < NE_) g_count[threadIdx.x] = 0; }

// transpose z [b][c][hw] -> [m][c] fp16 + zsq partials
__global__ void __launch_bounds__(256) k_prep_z(const float* __restrict__ z)
{
    __shared__ float tile[32][33];
    __shared__ float red[256];
    int hwt = blockIdx.x, ct = blockIdx.y, b = blockIdx.z;
    int tid = threadIdx.x, g = tid >> 5, lane = tid & 31;
    const float* zb = z + ((size_t)b*C_ + ct*32)*HW_ + hwt*32;
    float zs = 0.f;
#pragma unroll
    for (int i = 0; i < 4; i++) {
        int r = g + 8*i;                              // c_local
        float v = zb[(size_t)r*HW_ + lane];           // hw_local = lane
        tile[r][lane] = v;
        zs = fmaf(v, v, zs);
    }
    __syncthreads();
#pragma unroll
    for (int i = 0; i < 4; i++) {
        int r = g + 8*i;                              // hw_local
        float v = tile[lane][r];                      // c_local = lane
        size_t off = ((size_t)b*HW_ + hwt*32 + r)*C_ + ct*32 + lane;
        g_zh[off] = __float2half(v);
    }
    red[tid] = zs;
    __syncthreads();
    for (int st = 128; st > 0; st >>= 1) { if (tid < st) red[tid] += red[tid+st]; __syncthreads(); }
    if (tid == 0) g_zsqp[(blockIdx.z*32 + blockIdx.y)*32 + blockIdx.x] = red[0];
}

// emb: esq (double) + fp32 transpose + fp16 copy
__global__ void __launch_bounds__(256) k_prep_emb(const float* __restrict__ emb)
{
    __shared__ double red[256];
    int e = blockIdx.x, tid = threadIdx.x;
    float4 v = reinterpret_cast<const float4*>(emb + (size_t)e*C_)[tid];
    double s = (double)v.x*v.x + (double)v.y*v.y + (double)v.z*v.z + (double)v.w*v.w;
    int c = tid*4;
    float vv[4] = {v.x, v.y, v.z, v.w};
#pragma unroll
    for (int i = 0; i < 4; i++) {
        g_embT[(c+i)*NE_ + e] = vv[i];
        g_eh[e*C_ + c + i] = __float2half(vv[i]);
    }
    red[tid] = s;
    __syncthreads();
    for (int st = 128; st > 0; st >>= 1) { if (tid < st) red[tid] += red[tid+st]; __syncthreads(); }
    if (tid == 0) g_emb_sq[e] = (float)red[0];
}

__global__ void k_transpose_w(const float* __restrict__ W)
{
    __shared__ float sm[32][33];
    int c0 = blockIdx.x*32, o0 = blockIdx.y*32;
    int tx = threadIdx.x, ty = threadIdx.y;
#pragma unroll
    for (int i = 0; i < 4; i++)
        sm[ty + i*8][tx] = W[(size_t)(o0 + ty + i*8)*C_ + c0 + tx];
    __syncthreads();
#pragma unroll
    for (int i = 0; i < 4; i++)
        g_WT[(size_t)(c0 + ty + i*8)*C_ + o0 + tx] = sm[tx][ty + i*8];
}

// table partial: split-K x4
__global__ void __launch_bounds__(128) k_table(int dummy)
{
    __shared__ float As[32][32];
    __shared__ float Bs[32][64];
    int o0 = blockIdx.x*64, e0 = blockIdx.y*32, K0 = blockIdx.z*256;
    int tid = threadIdx.x, tx = tid & 15, ty = tid >> 4;
    float acc[4][4] = {};
    for (int kc = 0; kc < 8; kc++) {
#pragma unroll
        for (int s = 0; s < 2; s++) {
            int idx = tid + s*128, k = idx >> 3, f4 = idx & 7;
            reinterpret_cast<float4*>(&As[k][f4*4])[0] =
                reinterpret_cast<const float4*>(g_embT + (size_t)(K0 + kc*32 + k)*NE_ + e0)[f4];
        }
#pragma unroll
        for (int s = 0; s < 4; s++) {
            int idx = tid + s*128, k = idx >> 4, f4 = idx & 15;
            reinterpret_cast<float4*>(&Bs[k][f4*4])[0] =
                reinterpret_cast<const float4*>(g_WT + (size_t)(K0 + kc*32 + k)*C_ + o0)[f4];
        }
        __syncthreads();
#pragma unroll
        for (int k = 0; k < 32; k++) {
            float4 a = reinterpret_cast<float4*>(&As[k][ty*4])[0];
            float4 b = reinterpret_cast<float4*>(&Bs[k][tx*4])[0];
            float aa[4] = {a.x, a.y, a.z, a.w};
            float bb[4] = {b.x, b.y, b.z, b.w};
#pragma unroll
            for (int i = 0; i < 4; i++)
#pragma unroll
                for (int j = 0; j < 4; j++)
                    acc[i][j] = fmaf(aa[i], bb[j], acc[i][j]);
        }
        __syncthreads();
    }
#pragma unroll
    for (int i = 0; i < 4; i++)
#pragma unroll
        for (int j = 0; j < 4; j++)
            g_tpart[((size_t)blockIdx.z*NE_ + e0 + ty*4 + i)*C_ + o0 + tx*4 + j] = acc[i][j];
}

__global__ void __launch_bounds__(256) k_tcomb(const float* __restrict__ bias)
{
    int i = blockIdx.x*256 + threadIdx.x;
    float s = ((g_tpart[i] + g_tpart[i + NE_*C_]) + g_tpart[i + 2*NE_*C_]) + g_tpart[i + 3*NE_*C_];
    g_table[i] = s + bias[i & (C_-1)];
}

// ---- HMMA distance GEMM: scores[m][e] = esq[e] - 2 * z_m.e  (fp16 in, fp32 acc) ----
// CTA tile 128(M) x 128(N), K chunks of 32, cp.async double-buffer.
// smem rows stride 40 halfs (80B) -> ldmatrix bank-conflict-free.
__device__ __forceinline__ void fill_tiles(int tid, int m0, int n0, int kc,
                                           uint32_t aDst, uint32_t bDst)
{
#pragma unroll
    for (int s = 0; s < 4; s++) {
        int i = tid + s*256;
        int r = (i >> 2) & 127, ch = i & 3;
        if (i < 512)
            cpa16(aDst + (r*40 + ch*8)*2, g_zh + (size_t)(m0 + r)*C_ + kc*32 + ch*8);
        else
            cpa16(bDst + (r*40 + ch*8)*2, g_eh + (size_t)(n0 + r)*C_ + kc*32 + ch*8);
    }
}

__global__ void __launch_bounds__(256, 1) k_dist()
{
    __shared__ __align__(16) __half sA[2][128*40];
    __shared__ __align__(16) __half sB[2][128*40];
    __shared__ float esq_s[128];

    int tid = threadIdx.x, wid = tid >> 5, lane = tid & 31;
    int m0 = blockIdx.x*128, n0 = blockIdx.y*128;
    int warpM = wid & 3, warpN = wid >> 2;     // 4 x 2 warps -> 32 x 64 per warp

    if (tid < 128) esq_s[tid] = g_emb_sq[n0 + tid];

    uint32_t aBase[2] = { smem_to_u32(sA[0]), smem_to_u32(sA[1]) };
    uint32_t bBase[2] = { smem_to_u32(sB[0]), smem_to_u32(sB[1]) };

    float acc[2][8][4] = {};
    int buf = 0;
    fill_tiles(tid, m0, n0, 0, aBase[0], bBase[0]);
    CP_COMMIT();

    for (int kc = 0; kc < 32; kc++) {
        if (kc + 1 < 32) {
            fill_tiles(tid, m0, n0, kc + 1, aBase[buf^1], bBase[buf^1]);
            CP_COMMIT();
            CP_WAIT1();
        } else {
            CP_WAIT0();
        }
        __syncthreads();
        uint32_t sa = aBase[buf], sb = bBase[buf];
#pragma unroll
        for (int ks = 0; ks < 2; ks++) {
            uint32_t af[2][4], bfr[8][2];
#pragma unroll
            for (int mi = 0; mi < 2; mi++) {
                int lr  = warpM*32 + mi*16 + (lane & 7) + ((lane >> 3) & 1)*8;
                int chk = ks*2 + (lane >> 4);
                ldsm4(af[mi], sa + (lr*40 + chk*8)*2);
            }
#pragma unroll
            for (int nj = 0; nj < 4; nj++) {
                int lr  = warpN*64 + nj*16 + (lane & 7) + (lane >> 4)*8;
                int chk = ks*2 + ((lane >> 3) & 1);
                uint32_t t[4];
                ldsm4(t, sb + (lr*40 + chk*8)*2);
                bfr[nj*2][0]   = t[0]; bfr[nj*2][1]   = t[1];
                bfr[nj*2+1][0] = t[2]; bfr[nj*2+1][1] = t[3];
            }
#pragma unroll
            for (int mi = 0; mi < 2; mi++)
#pragma unroll
                for (int ni = 0; ni < 8; ni++)
                    mma16816(acc[mi][ni], af[mi], bfr[ni]);
        }
        __syncthreads();
        buf ^= 1;
    }

    // epilogue: score = esq - 2*dot, write float2 pairs
    int g = lane >> 2, t = lane & 3;
#pragma unroll
    for (int mi = 0; mi < 2; mi++) {
        int r0 = m0 + warpM*32 + mi*16 + g;
#pragma unroll
        for (int ni = 0; ni < 8; ni++) {
            int cl = warpN*64 + ni*8 + 2*t;
            float2 v0, v1;
            v0.x = fmaf(-2.f, acc[mi][ni][0], esq_s[cl]);
            v0.y = fmaf(-2.f, acc[mi][ni][1], esq_s[cl+1]);
            v1.x = fmaf(-2.f, acc[mi][ni][2], esq_s[cl]);
            v1.y = fmaf(-2.f, acc[mi][ni][3], esq_s[cl+1]);
            *(float2*)(g_scores + (size_t)r0*NE_ + n0 + cl)     = v0;
            *(float2*)(g_scores + (size_t)(r0+8)*NE_ + n0 + cl) = v1;
        }
    }
}

// ---- argmin + guaranteed-exact refine + histogram (warp per pixel) ----
__global__ void __launch_bounds__(256) k_argmin(const float* __restrict__ z,
                                                const float* __restrict__ emb,
                                                float* __restrict__ out, int extras)
{
    const unsigned full = 0xffffffffu;
    int warp = threadIdx.x >> 5, lane = threadIdx.x & 31;
    int m = blockIdx.x*8 + warp;
    const float* srow = g_scores + (size_t)m*NE_;

    float s[8];
    float4 a = reinterpret_cast<const float4*>(srow)[lane*2];
    float4 b4 = reinterpret_cast<const float4*>(srow)[lane*2 + 1];
    s[0]=a.x; s[1]=a.y; s[2]=a.z; s[3]=a.w; s[4]=b4.x; s[5]=b4.y; s[6]=b4.z; s[7]=b4.w;

    float b1v = 3.4e38f, b2v = 3.4e38f; int b1i = 0;
#pragma unroll
    for (int j = 0; j < 8; j++) {
        int col = lane*8 + j;
        if (s[j] < b1v) { b2v = b1v; b1v = s[j]; b1i = col; }
        else if (s[j] < b2v) b2v = s[j];
    }
#pragma unroll
    for (int off = 16; off > 0; off >>= 1) {
        float o1v = __shfl_xor_sync(full, b1v, off);
        int   o1i = __shfl_xor_sync(full, b1i, off);
        float o2v = __shfl_xor_sync(full, b2v, off);
        if (o1v < b1v || (o1v == b1v && o1i < b1i)) {
            b2v = fminf(b1v, o2v); b1v = o1v; b1i = o1i;
        } else {
            b2v = fminf(b2v, o1v);
        }
    }

    int winner; float wscore;
    if (b2v - b1v > MARGIN) {
        winner = b1i; wscore = b1v;
    } else {
        // exact fp32 refine over every code within MARGIN of the MMA best
        float thr = b1v + MARGIN;
        unsigned cmask = 0;
#pragma unroll
        for (int j = 0; j < 8; j++) if (s[j] <= thr) cmask |= 1u << j;
        int bb = m >> 10, hw = m & (HW_-1);
        const float* zp = z + (size_t)bb*C_*HW_ + hw;
        float bev = 3.4e38f; int bei = 0;
        for (int j = 0; j < 8; j++) {
            unsigned bal = __ballot_sync(full, (cmask >> j) & 1u);
            while (bal) {
                int sl = __ffs(bal) - 1; bal &= bal - 1;
                int col = sl*8 + j;
                const float* ep = emb + (size_t)col*C_;
                float acc = 0.f;
#pragma unroll
                for (int it = 0; it < 32; it++) {
                    int c = lane + it*32;
                    acc = fmaf(zp[(size_t)c*HW_], ep[c], acc);
                }
#pragma unroll
                for (int off = 16; off > 0; off >>= 1)
                    acc += __shfl_xor_sync(full, acc, off);
                float ex = fmaf(-2.f, acc, g_emb_sq[col]);
                if (ex < bev || (ex == bev && col < bei)) { bev = ex; bei = col; }
            }
        }
        winner = bei; wscore = bev;
    }
    if (lane == 0) {
        g_idx[m] = winner;
        g_minscore[m] = wscore;
        if (extras) out[NOUT_ + 2 + m] = (float)winner;
        atomicAdd(&g_count[winner], 1);
    }
}

// ---- loss + perplexity (fixed-order) ----
__global__ void __launch_bounds__(256) k_finalize(float* __restrict__ out, int extras)
{
    __shared__ float red[256];
    int tid = threadIdx.x;
    float sv = 0.f;
    for (int i = 0; i < 64; i++) sv += g_minscore[tid*64 + i];
    for (int i = 0; i < 64; i++) sv += g_zsqp[tid*64 + i];
    red[tid] = sv;
    __syncthreads();
    for (int st = 128; st > 0; st >>= 1) { if (tid < st) red[tid] += red[tid+st]; __syncthreads(); }
    float total = red[0];
    __syncthreads();
    float em = (float)g_count[tid] / (float)N_;
    red[tid] = em * logf(em + 1e-10f);
    __syncthreads();
    for (int st = 128; st > 0; st >>= 1) { if (tid < st) red[tid] += red[tid+st]; __syncthreads(); }
    if (tid == 0 && extras) {
        out[NOUT_]     = 1.25f * total / (float)NOUT_;
        out[NOUT_ + 1] = expf(-red[0]);
    }
}

// ---- output gather: out[b][o][hw] = table[idx[b,hw]][o] ----
__global__ void __launch_bounds__(256) k_out(float* __restrict__ out)
{
    __shared__ float tile[32][129];
    __shared__ int idxs[32];
    int o0 = blockIdx.x*128, hw0 = blockIdx.y*32, b = blockIdx.z;
    int tid = threadIdx.x;
    if (tid < 32) idxs[tid] = g_idx[b*HW_ + hw0 + tid];
    __syncthreads();
    for (int i = tid; i < 1024; i += 256) {
        int r = i >> 5, f4 = i & 31;
        float4 v = reinterpret_cast<const float4*>(g_table + (size_t)idxs[r]*C_ + o0)[f4];
        float* dst = &tile[r][f4*4];
        dst[0]=v.x; dst[1]=v.y; dst[2]=v.z; dst[3]=v.w;
    }
    __syncthreads();
    size_t base = (size_t)b*C_*HW_ + (size_t)o0*HW_ + hw0;
    for (int i = tid; i < 4096; i += 256) {
        int o = i >> 5, hw = i & 31;
        out[base + (size_t)o*HW_ + hw] = tile[hw][o];
    }
}

// ---------------- launcher ----------------
extern "C" void kernel_launch(void* const* d_in, const int* in_sizes, int n_in,
                              void* d_out, int out_size)
{
    (void)in_sizes; (void)n_in;
    const float* z    = (const float*)d_in[0];
    const float* emb  = (const float*)d_in[1];
    const float* W    = (const float*)d_in[2];
    const float* bias = (const float*)d_in[3];
    float* out = (float*)d_out;
    int extras = (out_size >= NOUT_ + 2 + N_) ? 1 : 0;

    k_init<<<1, 256>>>();
    k_prep_z<<<dim3(32, 32, 16), 256>>>(z);
    k_prep_emb<<<NE_, 256>>>(emb);
    k_transpose_w<<<dim3(32, 32), dim3(32, 8)>>>(W);
    k_table<<<dim3(16, 8, 4), 128>>>(0);
    k_tcomb<<<1024, 256>>>(bias);
    k_dist<<<dim3(128, 2), 256>>>();
    k_argmin<<<2048, 256>>>(z, emb, out, extras);
    k_finalize<<<1, 256>>>(out, extras);
    k_out<<<dim3(8, 32, 16), 256>>>(out);
}